// round 17
// baseline (speedup 1.0000x reference)
#include <cuda_runtime.h>

#define NB 2
#define NC 256
#define NL 1536
#define NH 4
#define ND 64
#define RR 50
#define NREL 101            // 2R+1
#define TT 16               // t-tile in attention kernel
#define SW (TT + 2*RR)      // 116: s-window per t-tile

// ---------------- scratch (device globals; no allocation) ----------------
__device__ float g_q  [NB*NH*NL*ND];
__device__ float g_k  [NB*NH*NL*ND];
__device__ float g_c  [NB*NH*NL*ND];
__device__ float g_att[NB*NC*NL];
__device__ float g_y  [NB*NC*NL];
__device__ float g_sum  [NC];
__device__ float g_sumsq[NC];

// ---------------- kernel 0: zero BN accumulators ----------------
__global__ void k_zero() {
    int i = threadIdx.x;
    if (i < NC) { g_sum[i] = 0.f; g_sumsq[i] = 0.f; }
}

// ================= tf32 MMA GEMM machinery =================
// D[o,l] = sum_c A[o,c] * B[c,l], CTA tile 32(o) x 128(l), K=256, slab 32.
// 8 warps laid 1x8 over l; per warp: 2 m-tiles x 2 n-tiles of m16n8k8.
// 3xTF32: hi/lo split staged into smem once per slab.

__device__ __forceinline__ unsigned f2tf(float x) {
    unsigned r; asm("cvt.rna.tf32.f32 %0, %1;" : "=r"(r) : "f"(x)); return r;
}

__device__ __forceinline__ void mma8(float d[4], const unsigned a[4], const unsigned b[2]) {
    asm volatile(
        "mma.sync.aligned.m16n8k8.row.col.f32.tf32.tf32.f32 "
        "{%0,%1,%2,%3},{%4,%5,%6,%7},{%8,%9},{%0,%1,%2,%3};"
        : "+f"(d[0]), "+f"(d[1]), "+f"(d[2]), "+f"(d[3])
        : "r"(a[0]), "r"(a[1]), "r"(a[2]), "r"(a[3]), "r"(b[0]), "r"(b[1]));
}

// smem float offsets: AH=0(1152) AL=1152 BH=2304(4224) BL=6528; total 10752 fl = 43008 B
#define GEMM_SMEM_FLOATS 10752

__device__ __forceinline__ void stage_slab(
    float* AH, float* AL, float* BH, float* BL,
    const float4& pa, const float4* pb, int tid)
{
    unsigned* AHu = (unsigned*)AH; unsigned* ALu = (unsigned*)AL;
    unsigned* BHu = (unsigned*)BH; unsigned* BLu = (unsigned*)BL;
    const int ao = tid >> 3, ac = (tid & 7) * 4;
    float va[4] = {pa.x, pa.y, pa.z, pa.w};
    #pragma unroll
    for (int i = 0; i < 4; i++) {
        unsigned hh = f2tf(va[i]);
        unsigned ll = f2tf(va[i] - __uint_as_float(hh));
        AHu[(ac + i) * 36 + ao] = hh;
        ALu[(ac + i) * 36 + ao] = ll;
    }
    #pragma unroll
    for (int i = 0; i < 4; i++) {
        int idx = i * 256 + tid;
        int c = idx >> 5, l4 = idx & 31;
        float vb[4] = {pb[i].x, pb[i].y, pb[i].z, pb[i].w};
        unsigned hh[4], ll[4];
        #pragma unroll
        for (int j = 0; j < 4; j++) {
            hh[j] = f2tf(vb[j]);
            ll[j] = f2tf(vb[j] - __uint_as_float(hh[j]));
        }
        *(uint4*)&BHu[c * 132 + l4 * 4] = make_uint4(hh[0], hh[1], hh[2], hh[3]);
        *(uint4*)&BLu[c * 132 + l4 * 4] = make_uint4(ll[0], ll[1], ll[2], ll[3]);
    }
}

// A: base at (o0,0), row stride NC. B: base at (0,l0), row stride NL.
__device__ __forceinline__ void gemm_tf32_mainloop(
    const float* __restrict__ A, const float* __restrict__ B,
    float* smem, float acc[2][2][4], int tid)
{
    float* AH = smem;
    float* AL = smem + 1152;
    float* BH = smem + 2304;
    float* BL = smem + 6528;
    const unsigned* AHu = (const unsigned*)AH;
    const unsigned* ALu = (const unsigned*)AL;
    const unsigned* BHu = (const unsigned*)BH;
    const unsigned* BLu = (const unsigned*)BL;

    const int lane = tid & 31, wid = tid >> 5;
    const int n0w = wid * 16;
    const int q = lane >> 2, qq = lane & 3;
    const int ao = tid >> 3, ac = (tid & 7) * 4;

    float4 pa; float4 pb[4];
    pa = *(const float4*)(A + ao * NC + ac);
    #pragma unroll
    for (int i = 0; i < 4; i++) {
        int idx = i * 256 + tid; int c = idx >> 5, l4 = idx & 31;
        pb[i] = *(const float4*)(B + (size_t)c * NL + l4 * 4);
    }
    stage_slab(AH, AL, BH, BL, pa, pb, tid);
    __syncthreads();

    #pragma unroll 1
    for (int s = 0; s < 8; s++) {
        if (s < 7) {
            pa = *(const float4*)(A + ao * NC + (s + 1) * 32 + ac);
            #pragma unroll
            for (int i = 0; i < 4; i++) {
                int idx = i * 256 + tid; int c = idx >> 5, l4 = idx & 31;
                pb[i] = *(const float4*)(B + (size_t)((s + 1) * 32 + c) * NL + l4 * 4);
            }
        }
        #pragma unroll
        for (int k8 = 0; k8 < 4; k8++) {
            const int kk = k8 * 8;
            const int base0 = (kk + qq) * 36, base4 = (kk + qq + 4) * 36;
            const int bb0 = (kk + qq) * 132,  bb4 = (kk + qq + 4) * 132;
            unsigned ah[2][4], alr[2][4], bh[2][2], blr[2][2];
            #pragma unroll
            for (int mt = 0; mt < 2; mt++) {
                int r = mt * 16 + q;
                ah[mt][0] = AHu[base0 + r];     ah[mt][1] = AHu[base0 + r + 8];
                ah[mt][2] = AHu[base4 + r];     ah[mt][3] = AHu[base4 + r + 8];
                alr[mt][0] = ALu[base0 + r];    alr[mt][1] = ALu[base0 + r + 8];
                alr[mt][2] = ALu[base4 + r];    alr[mt][3] = ALu[base4 + r + 8];
            }
            #pragma unroll
            for (int nt = 0; nt < 2; nt++) {
                int n = n0w + nt * 8 + q;
                bh[nt][0] = BHu[bb0 + n];   bh[nt][1] = BHu[bb4 + n];
                blr[nt][0] = BLu[bb0 + n];  blr[nt][1] = BLu[bb4 + n];
            }
            #pragma unroll
            for (int mt = 0; mt < 2; mt++)
                #pragma unroll
                for (int nt = 0; nt < 2; nt++) {
                    mma8(acc[mt][nt], alr[mt], bh[nt]);
                    mma8(acc[mt][nt], ah[mt],  blr[nt]);
                    mma8(acc[mt][nt], ah[mt],  bh[nt]);
                }
        }
        __syncthreads();
        if (s < 7) { stage_slab(AH, AL, BH, BL, pa, pb, tid); __syncthreads(); }
    }
}

// ---------------- kernel 1: fused projection GEMMs (tf32 MMA) ----------------
// grid (NL/128, 24, NB): wsel = by>>3, o0 = (by&7)*32 (o-tile within one head)
__global__ void __launch_bounds__(256) k_proj3(
    const float* __restrict__ Wc, const float* __restrict__ bc,
    const float* __restrict__ Wq, const float* __restrict__ bq,
    const float* __restrict__ Wk, const float* __restrict__ bk,
    const float* __restrict__ x)
{
    extern __shared__ float smem[];
    const int l0 = blockIdx.x * 128;
    const int wsel = blockIdx.y >> 3;
    const int o0 = (blockIdx.y & 7) * 32;
    const int b  = blockIdx.z;
    const int tid = threadIdx.x;
    const int lane = tid & 31, wid = tid >> 5;
    const int n0w = wid * 16;
    const int q = lane >> 2, qq = lane & 3;

    const float* W    = (wsel == 0) ? Wc : (wsel == 1) ? Wq : Wk;
    const float* bias = (wsel == 0) ? bc : (wsel == 1) ? bq : bk;
    float* outT       = (wsel == 0) ? g_c : (wsel == 1) ? g_q : g_k;

    float acc[2][2][4] = {};
    gemm_tf32_mainloop(W + o0 * NC, x + (size_t)b * NC * NL + l0, smem, acc, tid);

    // stage transposed [l][o_local] (alias smem; last mainloop sync protects reads)
    float* sT = smem;   // 128 x 36
    #pragma unroll
    for (int mt = 0; mt < 2; mt++) {
        int r = mt * 16 + q;
        float bv0 = bias[o0 + r], bv1 = bias[o0 + r + 8];
        #pragma unroll
        for (int nt = 0; nt < 2; nt++) {
            int c = n0w + nt * 8 + 2 * qq;
            sT[c * 36 + r]           = acc[mt][nt][0] + bv0;
            sT[(c + 1) * 36 + r]     = acc[mt][nt][1] + bv0;
            sT[c * 36 + r + 8]       = acc[mt][nt][2] + bv1;
            sT[(c + 1) * 36 + r + 8] = acc[mt][nt][3] + bv1;
        }
    }
    __syncthreads();

    const int h = o0 >> 6, dbase = o0 & 63;
    float* dst = outT + ((size_t)(b * NH + h) * NL + l0) * ND + dbase;
    #pragma unroll
    for (int it = 0; it < 4; it++) {
        int idx = it * 256 + tid;
        int l = idx >> 3, dq = (idx & 7) * 4;
        *(float4*)&dst[(size_t)l * ND + dq] = *(const float4*)&sT[l * 36 + dq];
    }
}

// ---------------- kernel 2: banded attention, register-tiled passes ----------------
// grid (NL/TT, NH, NB), 256 threads, ~82.8KB dynamic smem.
__global__ void __launch_bounds__(256) k_attn(const float* __restrict__ emb)
{
    extern __shared__ float smem[];
    float (*sQ  )[68]   = (float(*)[68] )(smem);                         // 16 x 68
    float (*sKC )[68]   = (float(*)[68] )(smem + TT*68);                 // 116 x 68
    float (*sEmb)[68]   = (float(*)[68] )(smem + (TT+SW)*68);            // 101 x 68
    float (*sS  )[120]  = (float(*)[120])(smem + (TT+SW+NREL)*68);       // 16 x 120
    float (*sG  )[104]  = (float(*)[104])(smem + (TT+SW+NREL)*68 + TT*120); // 16 x 104
    float (*sOut)[20]   = (float(*)[20] )(smem + (TT+SW+NREL)*68 + TT*120 + TT*104); // 64 x 20

    const int t0 = blockIdx.x * TT;
    const int bh = blockIdx.z * NH + blockIdx.y;
    const int tid = threadIdx.x;
    const int s0 = t0 - RR;

    const float* qb = g_q + (size_t)(bh*NL + t0) * ND;
    {
        int i = tid;
        int r = i >> 4, dq = (i & 15) * 4;
        *(float4*)&sQ[r][dq] = *(const float4*)&qb[r*64 + dq];
    }
    const float* kb = g_k + (size_t)bh * NL * ND;
    for (int i = tid; i < SW*16; i += 256) {
        int j = i >> 4, dq = (i & 15) * 4;
        int s = s0 + j;
        float4 v = make_float4(0.f,0.f,0.f,0.f);
        if (s >= 0 && s < NL) v = *(const float4*)&kb[(size_t)s*64 + dq];
        *(float4*)&sKC[j][dq] = v;
    }
    for (int i = tid; i < NREL*16; i += 256) {
        int r = i >> 4, dq = (i & 15) * 4;
        float4 v = *(const float4*)&emb[r*64 + dq];
        v.x *= 0.3f; v.y *= 0.3f; v.z *= 0.3f; v.w *= 0.3f;
        *(float4*)&sEmb[r][dq] = v;
    }
    __syncthreads();

    // G-pass
    {
        int tg = tid >> 5, lane = tid & 31;
        if (lane < 26) {
            int tt0 = tg * 2;
            float acc0[4] = {}, acc1[4] = {};
            for (int d = 0; d < 64; d += 4) {
                float4 q0 = *(const float4*)&sQ[tt0  ][d];
                float4 q1 = *(const float4*)&sQ[tt0+1][d];
                #pragma unroll
                for (int i = 0; i < 4; i++) {
                    int r = lane + 26*i;
                    if (r < NREL) {
                        float4 e = *(const float4*)&sEmb[r][d];
                        acc0[i] += q0.x*e.x + q0.y*e.y + q0.z*e.z + q0.w*e.w;
                        acc1[i] += q1.x*e.x + q1.y*e.y + q1.z*e.z + q1.w*e.w;
                    }
                }
            }
            #pragma unroll
            for (int i = 0; i < 4; i++) {
                int r = lane + 26*i;
                if (r < NREL) { sG[tt0][r] = acc0[i]; sG[tt0+1][r] = acc1[i]; }
            }
        }
    }
    __syncthreads();

    // S-pass
    {
        int tg = tid >> 5, lane = tid & 31;
        if (lane < 29) {
            int tt0 = tg * 2;
            float acc0[4] = {}, acc1[4] = {};
            for (int d = 0; d < 64; d += 4) {
                float4 q0 = *(const float4*)&sQ[tt0  ][d];
                float4 q1 = *(const float4*)&sQ[tt0+1][d];
                #pragma unroll
                for (int i = 0; i < 4; i++) {
                    int j = lane + 29*i;
                    float4 k4 = *(const float4*)&sKC[j][d];
                    acc0[i] += q0.x*k4.x + q0.y*k4.y + q0.z*k4.z + q0.w*k4.w;
                    acc1[i] += q1.x*k4.x + q1.y*k4.y + q1.z*k4.z + q1.w*k4.w;
                }
            }
            #pragma unroll
            for (int i = 0; i < 4; i++) {
                int j = lane + 29*i;
                int s = s0 + j;
                #pragma unroll
                for (int ii = 0; ii < 2; ii++) {
                    int tt = tt0 + ii;
                    float v = -1e30f;
                    if (s >= 0 && s < NL && j >= tt && j <= tt + 2*RR)
                        v = (ii ? acc1[i] : acc0[i]) + sG[tt][tt + 2*RR - j];
                    sS[tt][j] = v;
                }
            }
        }
    }
    __syncthreads();

    // overwrite K with content
    const float* cb = g_c + (size_t)bh * NL * ND;
    for (int i = tid; i < SW*16; i += 256) {
        int j = i >> 4, dq = (i & 15) * 4;
        int s = s0 + j;
        float4 v = make_float4(0.f,0.f,0.f,0.f);
        if (s >= 0 && s < NL) v = *(const float4*)&cb[(size_t)s*64 + dq];
        *(float4*)&sKC[j][dq] = v;
    }

    // softmax
    {
        int w = tid >> 5, lane = tid & 31;
        for (int tt = w; tt < TT; tt += 8) {
            float m = -1e30f;
            for (int j = lane; j < SW; j += 32) m = fmaxf(m, sS[tt][j]);
            #pragma unroll
            for (int o = 16; o; o >>= 1) m = fmaxf(m, __shfl_xor_sync(0xffffffffu, m, o));
            float sum = 0.f;
            for (int j = lane; j < SW; j += 32) {
                float e = __expf(sS[tt][j] - m);
                sS[tt][j] = e;
                sum += e;
            }
            #pragma unroll
            for (int o = 16; o; o >>= 1) sum += __shfl_xor_sync(0xffffffffu, sum, o);
            float inv = 1.f / sum;
            for (int j = lane; j < SW; j += 32) sS[tt][j] *= inv;
        }
    }
    __syncthreads();

    // O-pass
    {
        int tt = tid >> 4, c = (tid & 15) * 4;
        float ax = 0.f, ay = 0.f, az = 0.f, aw = 0.f;
        #pragma unroll 4
        for (int jj = 0; jj < NREL; jj++) {
            float w = sS[tt][tt + jj];
            float4 cv = *(const float4*)&sKC[tt + jj][c];
            float4 ev = *(const float4*)&sEmb[2*RR - jj][c];
            ax += w * (cv.x + ev.x);
            ay += w * (cv.y + ev.y);
            az += w * (cv.z + ev.z);
            aw += w * (cv.w + ev.w);
        }
        sOut[c+0][tt] = ax; sOut[c+1][tt] = ay;
        sOut[c+2][tt] = az; sOut[c+3][tt] = aw;
    }
    __syncthreads();

    {
        float* ob = g_att + (size_t)blockIdx.z * NC * NL + (size_t)blockIdx.y * 64 * NL;
        int c = tid >> 2, i4 = (tid & 3) * 4;
        *(float4*)&ob[(size_t)c * NL + t0 + i4] = *(const float4*)&sOut[c][i4];
    }
}

// ---------------- kernel 3: final projection (tf32 MMA) + bias + BN stats ----------------
// grid (NL/128, NC/32, NB) = 192.
__global__ void __launch_bounds__(256) k_final(
    const float* __restrict__ W, const float* __restrict__ bias)
{
    extern __shared__ float smem[];
    const int l0 = blockIdx.x * 128;
    const int o0 = blockIdx.y * 32;
    const int b  = blockIdx.z;
    const int tid = threadIdx.x;
    const int lane = tid & 31, wid = tid >> 5;
    const int n0w = wid * 16;
    const int q = lane >> 2, qq = lane & 3;

    float acc[2][2][4] = {};
    gemm_tf32_mainloop(W + o0 * NC, g_att + (size_t)b * NC * NL + l0, smem, acc, tid);

    float* yb = g_y + (size_t)b * NC * NL;
    #pragma unroll
    for (int mt = 0; mt < 2; mt++) {
        int r = mt * 16 + q;
        #pragma unroll
        for (int rr2 = 0; rr2 < 2; rr2++) {
            int o = o0 + r + rr2 * 8;
            float bv = bias[o];
            float s1 = 0.f, s2 = 0.f;
            #pragma unroll
            for (int nt = 0; nt < 2; nt++) {
                float d0 = acc[mt][nt][rr2*2 + 0] + bv;
                float d1 = acc[mt][nt][rr2*2 + 1] + bv;
                int c = n0w + nt * 8 + 2 * qq;
                *(float2*)&yb[(size_t)o * NL + l0 + c] = make_float2(d0, d1);
                s1 += d0 + d1;
                s2 += d0*d0 + d1*d1;
            }
            s1 += __shfl_xor_sync(0xffffffffu, s1, 1);
            s2 += __shfl_xor_sync(0xffffffffu, s2, 1);
            s1 += __shfl_xor_sync(0xffffffffu, s1, 2);
            s2 += __shfl_xor_sync(0xffffffffu, s2, 2);
            if (qq == 0) {
                atomicAdd(&g_sum[o],   s1);
                atomicAdd(&g_sumsq[o], s2);
            }
        }
    }
}

// ---------------- kernel 4: BN finalize + ReLU + scale (float4) ----------------
__global__ void __launch_bounds__(256) k_bn(
    const float* __restrict__ gamma, const float* __restrict__ beta,
    const float* __restrict__ scale, float* __restrict__ out)
{
    int idx4 = blockIdx.x * 256 + threadIdx.x;
    if (idx4 >= NB*NC*NL/4) return;
    int ch = (idx4 / (NL/4)) & (NC - 1);
    const float invN = 1.f / (float)(NB * NL);
    float mean = g_sum[ch] * invN;
    float var  = g_sumsq[ch] * invN - mean * mean;
    float a = rsqrtf(var + 1e-5f) * gamma[ch];
    float bta = beta[ch], sc = scale[ch];
    float4 v = *(const float4*)&g_y[idx4 * 4];
    float4 r;
    r.x = fmaxf((v.x - mean) * a + bta, 0.f) * sc;
    r.y = fmaxf((v.y - mean) * a + bta, 0.f) * sc;
    r.z = fmaxf((v.z - mean) * a + bta, 0.f) * sc;
    r.w = fmaxf((v.w - mean) * a + bta, 0.f) * sc;
    *(float4*)&out[idx4 * 4] = r;
}

// ---------------- launch ----------------
extern "C" void kernel_launch(void* const* d_in, const int* in_sizes, int n_in,
                              void* d_out, int out_size)
{
    const float* x     = (const float*)d_in[0];
    const float* Wc    = (const float*)d_in[1];
    const float* bc    = (const float*)d_in[2];
    const float* Wq    = (const float*)d_in[3];
    const float* bq    = (const float*)d_in[4];
    const float* Wk    = (const float*)d_in[5];
    const float* bk    = (const float*)d_in[6];
    const float* emb   = (const float*)d_in[7];
    const float* Wf    = (const float*)d_in[8];
    const float* bf    = (const float*)d_in[9];
    const float* gamma = (const float*)d_in[10];
    const float* beta  = (const float*)d_in[11];
    const float* scale = (const float*)d_in[12];
    float* out = (float*)d_out;

    const int SMEM_GEMM = GEMM_SMEM_FLOATS * (int)sizeof(float);   // 43008 B
    const int SMEM_ATTN = ((TT + SW + NREL)*68 + TT*120 + TT*104 + 64*20) * (int)sizeof(float);
    cudaFuncSetAttribute(k_attn, cudaFuncAttributeMaxDynamicSharedMemorySize, SMEM_ATTN);

    k_zero<<<1, 256>>>();

    dim3 gP(NL/128, 24, NB);
    k_proj3<<<gP, 256, SMEM_GEMM>>>(Wc, bc, Wq, bq, Wk, bk, x);

    dim3 gA(NL/TT, NH, NB);
    k_attn<<<gA, 256, SMEM_ATTN>>>(emb);

    dim3 gF(NL/128, NC/32, NB);
    k_final<<<gF, 256, SMEM_GEMM>>>(Wf, bf);

    int total4 = NB*NC*NL/4;
    k_bn<<<(total4 + 255)/256, 256>>>(gamma, beta, scale, out);
}